// round 4
// baseline (speedup 1.0000x reference)
#include <cuda_runtime.h>
#include <math.h>
#include <stdint.h>

// Problem constants
#define TT   256
#define BB   32
#define DD   512
#define HH   8
#define HDd  64
#define ETA  4
#define RR   4
#define FEAT 256
#define MM   (TT*BB)        // 8192
#define NPROJ2 2688         // 5*H*HD + 3*H*ETA + 32 pad  (21*128)
#define WROWS  2560         // 5*H*HD

// Scratch (device globals; allocation-free per harness rules)
__device__ float g_x   [(size_t)MM * DD];        // tf32-rounded inputs
__device__ float g_w5  [(size_t)NPROJ2 * DD];    // tf32 Wq|Wk|Wv|Wb|Wg|Wp1|Wp2|Wp3|0
__device__ float g_wo  [(size_t)DD * DD];        // tf32-rounded Wo
__device__ float g_proj[(size_t)MM * NPROJ2];
__device__ float g_attn[(size_t)MM * DD];        // tf32-rounded attn

__device__ __forceinline__ float tf32r(float x) {
    float r;
    asm("cvt.rna.tf32.f32 %0, %1;" : "=f"(r) : "f"(x));
    return r;
}

__global__ void cvt1_kernel(float* __restrict__ dst, const float* __restrict__ src, int n) {
    int i = blockIdx.x * 256 + threadIdx.x;
    if (i < n) dst[i] = tf32r(src[i]);
}
__global__ void cvt5_kernel(float* __restrict__ dst,
                            const float* __restrict__ s0, const float* __restrict__ s1,
                            const float* __restrict__ s2, const float* __restrict__ s3,
                            const float* __restrict__ s4, int per) {
    int i = blockIdx.x * 256 + threadIdx.x;
    if (i >= 5 * per) return;
    int seg = i / per, j = i - seg * per;
    const float* s = (seg == 0) ? s0 : (seg == 1) ? s1 : (seg == 2) ? s2 : (seg == 3) ? s3 : s4;
    dst[i] = tf32r(s[j]);
}
__global__ void cvtp_kernel(float* __restrict__ dst,   // dst = g_w5 + WROWS*DD
                            const float* __restrict__ s0, const float* __restrict__ s1,
                            const float* __restrict__ s2, int per) {
    int i = blockIdx.x * 256 + threadIdx.x;
    if (i >= 4 * per) return;
    int seg = i / per, j = i - seg * per;
    float v = 0.f;
    if (seg == 0) v = tf32r(s0[j]);
    else if (seg == 1) v = tf32r(s1[j]);
    else if (seg == 2) v = tf32r(s2[j]);
    dst[i] = v;
}

// ---------------------------------------------------------------------------
// TF32 tensor-core GEMM: C[M x N] = A[M x K] @ B[N x K]^T (+bias)
// 3-stage cp.async pipeline, one __syncthreads per K-iter.
// ---------------------------------------------------------------------------
#define GBM 128
#define GBN 128
#define GBK 16
#define KPAD 20
#define STG 3

__global__ __launch_bounds__(256) void mma_gemm(
    const float* __restrict__ A, const float* __restrict__ B,
    float* __restrict__ C, int M, int N, int K, const float* __restrict__ bias)
{
    __shared__ float As[STG][GBM * KPAD];
    __shared__ float Bs[STG][GBN * KPAD];

    const int tid  = threadIdx.x;
    const int lane = tid & 31;
    const int wid  = tid >> 5;
    const int wm   = wid & 1;
    const int wn   = wid >> 1;
    const int m0   = blockIdx.y * GBM;
    const int n0   = blockIdx.x * GBN;

    const unsigned asbase = (unsigned)__cvta_generic_to_shared(&As[0][0]);
    const unsigned bsbase = (unsigned)__cvta_generic_to_shared(&Bs[0][0]);

    const int a_r  = lane & 15;
    const int a_k4 = (lane >> 4) * 4;
    const int b_n  = lane & 7;
    const int b_k4 = (lane >> 3) * 4;

    float acc[4][4][4];
#pragma unroll
    for (int i = 0; i < 4; i++)
#pragma unroll
        for (int j = 0; j < 4; j++)
#pragma unroll
            for (int c = 0; c < 4; c++) acc[i][j][c] = 0.f;

    auto prefetch = [&](int it, int buf) {
        const int k0 = it * GBK;
#pragma unroll
        for (int i = 0; i < 2; i++) {
            int idx = tid + i * 256;
            int r   = idx >> 2;
            int k4  = (idx & 3) * 4;
            unsigned da = asbase + (unsigned)((buf * GBM * KPAD + r * KPAD + k4) * 4);
            const float* sa = A + (size_t)(m0 + r) * K + k0 + k4;
            asm volatile("cp.async.ca.shared.global [%0], [%1], 16;\n" :: "r"(da), "l"(sa));
            unsigned db = bsbase + (unsigned)((buf * GBN * KPAD + r * KPAD + k4) * 4);
            const float* sb = B + (size_t)(n0 + r) * K + k0 + k4;
            asm volatile("cp.async.ca.shared.global [%0], [%1], 16;\n" :: "r"(db), "l"(sb));
        }
        asm volatile("cp.async.commit_group;\n");
    };

    const int NIT = K / GBK;
    prefetch(0, 0);
    if (NIT > 1) prefetch(1, 1);

    int buf = 0, pf = 2;
    for (int it = 0; it < NIT; ++it) {
        if (it + 1 < NIT) {
            asm volatile("cp.async.wait_group 1;\n");
        } else {
            asm volatile("cp.async.wait_group 0;\n");
        }
        __syncthreads();   // single barrier per iter (stage ring distance 3)

        uint32_t bf[4][4];
#pragma unroll
        for (int nt = 0; nt < 4; nt++) {
            unsigned addr = bsbase + (unsigned)((buf * GBN * KPAD +
                            (wn * 32 + nt * 8 + b_n) * KPAD + b_k4) * 4);
            asm volatile("ldmatrix.sync.aligned.m8n8.x4.shared.b16 {%0,%1,%2,%3}, [%4];"
                : "=r"(bf[nt][0]), "=r"(bf[nt][1]), "=r"(bf[nt][2]), "=r"(bf[nt][3])
                : "r"(addr));
        }

#pragma unroll
        for (int k8 = 0; k8 < 2; k8++) {
            uint32_t af[4][4];
#pragma unroll
            for (int mt = 0; mt < 4; mt++) {
                unsigned addr = asbase + (unsigned)((buf * GBM * KPAD +
                                (wm * 64 + mt * 16 + a_r) * KPAD + k8 * 8 + a_k4) * 4);
                asm volatile("ldmatrix.sync.aligned.m8n8.x4.shared.b16 {%0,%1,%2,%3}, [%4];"
                    : "=r"(af[mt][0]), "=r"(af[mt][1]), "=r"(af[mt][2]), "=r"(af[mt][3])
                    : "r"(addr));
            }
#pragma unroll
            for (int mt = 0; mt < 4; mt++)
#pragma unroll
                for (int nt = 0; nt < 4; nt++) {
                    asm volatile(
                        "mma.sync.aligned.m16n8k8.row.col.f32.tf32.tf32.f32 "
                        "{%0,%1,%2,%3}, {%4,%5,%6,%7}, {%8,%9}, {%0,%1,%2,%3};"
                        : "+f"(acc[mt][nt][0]), "+f"(acc[mt][nt][1]),
                          "+f"(acc[mt][nt][2]), "+f"(acc[mt][nt][3])
                        : "r"(af[mt][0]), "r"(af[mt][1]), "r"(af[mt][2]), "r"(af[mt][3]),
                          "r"(bf[nt][k8 * 2]), "r"(bf[nt][k8 * 2 + 1]));
                }
        }

        if (it + 2 < NIT) prefetch(it + 2, pf);
        buf = (buf + 1 == STG) ? 0 : buf + 1;
        pf  = (pf  + 1 == STG) ? 0 : pf + 1;
    }

#pragma unroll
    for (int mt = 0; mt < 4; mt++) {
        int row = m0 + wm * 64 + mt * 16 + (lane >> 2);
#pragma unroll
        for (int nt = 0; nt < 4; nt++) {
            int col = n0 + wn * 32 + nt * 8 + (lane & 3) * 2;
            float b0v = bias ? bias[col]     : 0.f;
            float b1v = bias ? bias[col + 1] : 0.f;
            float2 v0 = make_float2(acc[mt][nt][0] + b0v, acc[mt][nt][1] + b1v);
            float2 v1 = make_float2(acc[mt][nt][2] + b0v, acc[mt][nt][3] + b1v);
            *reinterpret_cast<float2*>(&C[(size_t)row * N + col]) = v0;
            *reinterpret_cast<float2*>(&C[(size_t)(row + 8) * N + col]) = v1;
        }
    }
}

// ---------------------------------------------------------------------------
// Recurrence kernel v3: 512 threads = two (b,h) pairs per block (one wave),
// per-half named barriers, cp.async double-buffered staging.
// ---------------------------------------------------------------------------
__device__ __forceinline__ float sigf(float x) {
    return 1.f / (1.f + __expf(-x));
}

__global__ __launch_bounds__(512) void recur_kernel(
    const float* __restrict__ proj,   // [MM][2688] q|k|v|b|g|p1|p2|p3
    const int*   __restrict__ term,   // [MM]
    const float* __restrict__ tkp,    // (B,R,H,FEAT)
    const float* __restrict__ tvp,    // (B,R,H,HD)
    const float* __restrict__ sprev,  // (B,H,FEAT)
    const float* __restrict__ tick,   // (B,)
    float* __restrict__ attn)         // [MM][512], tf32-rounded on write
{
    const int tid512 = threadIdx.x;
    const int half = tid512 >> 8;     // 0 or 1
    const int tid = tid512 & 255;
    const int bh = blockIdx.x * 2 + half;
    const int b = bh >> 3;
    const int h = bh & 7;
    const int e = tid >> 6;
    const int d = tid & 63;

    __shared__ __align__(16) float sstage[2][2][5][64];
    __shared__ __align__(16) float sp[2][2][3][4];
    __shared__ int sterm[2][2];
    __shared__ float red[2][5][8];
    __shared__ float kvbuf[2][256];

#define BARH() asm volatile("bar.sync %0, 256;" :: "r"(1 + half) : "memory")

    float ks0 = tkp[((size_t)(b * RR + 0) * HH + h) * FEAT + tid];
    float ks1 = tkp[((size_t)(b * RR + 1) * HH + h) * FEAT + tid];
    float ks2 = tkp[((size_t)(b * RR + 2) * HH + h) * FEAT + tid];
    float ks3 = tkp[((size_t)(b * RR + 3) * HH + h) * FEAT + tid];
    float vs  = tvp[((size_t)(b * RR + e) * HH + h) * HDd + d];
    float ss  = sprev[((size_t)(b * HH + h)) * FEAT + tid];

    const float PI = 3.14159265358979323846f;
    const float tk = tick[b];

    float cr0, cr1, cr2, cr3, sr0, sr1, sr2, sr3;
    float cw0, cw1, cw2, cw3, sw0, sw1, sw2, sw3;
    {
        float om0 = -PI;
        float om1 = -PI + 2.f * PI / 3.f;
        float om2 = -PI + 4.f * PI / 3.f;
        float om3 = PI;
        float a;
        a = (1.f + tk) * om0; cr0 = cosf(a); sr0 = sinf(a);
        a = (1.f + tk) * om1; cr1 = cosf(a); sr1 = sinf(a);
        a = (1.f + tk) * om2; cr2 = cosf(a); sr2 = sinf(a);
        a = (1.f + tk) * om3; cr3 = cosf(a); sr3 = sinf(a);
        cw0 = cosf(om0); sw0 = sinf(om0);
        cw1 = cosf(om1); sw1 = sinf(om1);
        cw2 = cosf(om2); sw2 = sinf(om2);
        cw3 = cosf(om3); sw3 = sinf(om3);
    }

    auto stage = [&](int t, int buf) {
        const int m = t * BB + b;
        if (tid < 80) {
            const int seg = tid >> 4;
            const int j = (tid & 15) * 4;
            const float* src = proj + (size_t)m * NPROJ2 + seg * 512 + h * HDd + j;
            unsigned dst = (unsigned)__cvta_generic_to_shared(&sstage[half][buf][seg][j]);
            asm volatile("cp.async.ca.shared.global [%0], [%1], 16;\n" :: "r"(dst), "l"(src));
        } else if (tid < 83) {
            const int j = tid - 80;
            const float* src = proj + (size_t)m * NPROJ2 + WROWS + j * 32 + h * ETA;
            unsigned dst = (unsigned)__cvta_generic_to_shared(&sp[half][buf][j][0]);
            asm volatile("cp.async.ca.shared.global [%0], [%1], 16;\n" :: "r"(dst), "l"(src));
        } else if (tid == 83) {
            const int* src = term + m;
            unsigned dst = (unsigned)__cvta_generic_to_shared(&sterm[half][buf]);
            asm volatile("cp.async.ca.shared.global [%0], [%1], 4;\n" :: "r"(dst), "l"(src));
        }
        asm volatile("cp.async.commit_group;\n");
    };

    stage(0, 0);

    for (int t = 0; t < TT; t++) {
        const int buf = t & 1;
        if (t + 1 < TT) {
            stage(t + 1, buf ^ 1);
            asm volatile("cp.async.wait_group 1;\n");
        } else {
            asm volatile("cp.async.wait_group 0;\n");
        }
        BARH();   // S1

        const float qd = sstage[half][buf][0][d];
        const float kd = sstage[half][buf][1][d];
        const float vv = sstage[half][buf][2][d];
        const float bd = sigf(sstage[half][buf][3][d]);
        const float gd = sigf(sstage[half][buf][4][d]);
        const float p1e = sp[half][buf][0][e];
        const float p2e = sp[half][buf][1][e];
        const float p3e = sigf(sp[half][buf][2][e]);
        const float tf = 1.f - (float)sterm[half][buf];

        const float phi = fmaxf(qd * p2e, 0.f);
        const float psi = fmaxf(kd * p1e, 0.f);
        const float gf  = gd * p3e;
        const float gk  = psi * gf;
        const float dg  = (1.f - gf) * tf;

        ss = dg * ss + gk;
        float v4 = ss * phi;

        ks0 = dg * ks0 + gk * cr0;
        ks1 = dg * ks1 + gk * cr1;
        ks2 = dg * ks2 + gk * cr2;
        ks3 = dg * ks3 + gk * cr3;
        float v0 = ks0 * phi;
        float v1 = ks1 * phi;
        float v2 = ks2 * phi;
        float v3 = ks3 * phi;

        const float ce = (e == 0) ? cr0 : (e == 1) ? cr1 : (e == 2) ? cr2 : cr3;
        vs = (1.f - bd) * tf * vs + (vv * bd) * ce;

#pragma unroll
        for (int o = 16; o > 0; o >>= 1) {
            v0 += __shfl_down_sync(0xffffffffu, v0, o);
            v1 += __shfl_down_sync(0xffffffffu, v1, o);
            v2 += __shfl_down_sync(0xffffffffu, v2, o);
            v3 += __shfl_down_sync(0xffffffffu, v3, o);
            v4 += __shfl_down_sync(0xffffffffu, v4, o);
        }
        const int warp = tid >> 5;
        if ((tid & 31) == 0) {
            red[half][0][warp] = v0;
            red[half][1][warp] = v1;
            red[half][2][warp] = v2;
            red[half][3][warp] = v3;
            red[half][4][warp] = v4;
        }
        BARH();   // S2

        float kdq_e = 0.f, norm = 0.f;
#pragma unroll
        for (int w = 0; w < 8; w++) {
            kdq_e += red[half][e][w];
            norm  += red[half][4][w];
        }

        kvbuf[half][tid] = vs * kdq_e;
        BARH();   // S3

        if (tid < 64) {
            const int m = t * BB + b;
            float kv = kvbuf[half][tid] + kvbuf[half][tid + 64]
                     + kvbuf[half][tid + 128] + kvbuf[half][tid + 192];
            attn[(size_t)m * DD + h * HDd + tid] = tf32r(kv / (8.f * norm + 1e-6f));
        }

        float c2, s2;
        c2 = cr0 * cw0 - sr0 * sw0; s2 = sr0 * cw0 + cr0 * sw0; cr0 = c2; sr0 = s2;
        c2 = cr1 * cw1 - sr1 * sw1; s2 = sr1 * cw1 + cr1 * sw1; cr1 = c2; sr1 = s2;
        c2 = cr2 * cw2 - sr2 * sw2; s2 = sr2 * cw2 + cr2 * sw2; cr2 = c2; sr2 = s2;
        c2 = cr3 * cw3 - sr3 * sw3; s2 = sr3 * cw3 + cr3 * sw3; cr3 = c2; sr3 = s2;
    }
#undef BARH
}

// ---------------------------------------------------------------------------
extern "C" void kernel_launch(void* const* d_in, const int* in_sizes, int n_in,
                              void* d_out, int out_size)
{
    const float* inputs = (const float*)d_in[0];
    const int*   term   = (const int*)d_in[1];
    const float* tkp    = (const float*)d_in[2];
    const float* tvp    = (const float*)d_in[3];
    const float* sprev  = (const float*)d_in[4];
    const float* tick   = (const float*)d_in[5];
    const float* Wq     = (const float*)d_in[6];
    const float* Wk     = (const float*)d_in[7];
    const float* Wv     = (const float*)d_in[8];
    const float* Wb     = (const float*)d_in[9];
    const float* Wg     = (const float*)d_in[10];
    const float* Wp1    = (const float*)d_in[11];
    const float* Wp2    = (const float*)d_in[12];
    const float* Wp3    = (const float*)d_in[13];
    const float* Wo     = (const float*)d_in[14];
    const float* bo     = (const float*)d_in[15];

    void* p;
    cudaGetSymbolAddress(&p, g_x);    float* x    = (float*)p;
    cudaGetSymbolAddress(&p, g_w5);   float* w5   = (float*)p;
    cudaGetSymbolAddress(&p, g_wo);   float* wo   = (float*)p;
    cudaGetSymbolAddress(&p, g_proj); float* proj = (float*)p;
    cudaGetSymbolAddress(&p, g_attn); float* attn = (float*)p;

    const int WSZ = HH * HDd * DD;    // 262144
    const int PSZ = HH * ETA * DD;    // 16384

    cvt1_kernel<<<(MM * DD + 255) / 256, 256>>>(x, inputs, MM * DD);
    cvt5_kernel<<<(5 * WSZ + 255) / 256, 256>>>(w5, Wq, Wk, Wv, Wb, Wg, WSZ);
    cvtp_kernel<<<(4 * PSZ + 255) / 256, 256>>>(w5 + (size_t)WROWS * DD, Wp1, Wp2, Wp3, PSZ);
    cvt1_kernel<<<(WSZ + 255) / 256, 256>>>(wo, Wo, WSZ);

    // 1) Fused projection: (8192 x 2688) — q,k,v,beta,gamma,p1,p2,p3
    {
        dim3 grid(NPROJ2 / GBN, MM / GBM);
        mma_gemm<<<grid, 256>>>(x, w5, proj, MM, NPROJ2, DD, nullptr);
    }
    // 2) Recurrence (two bh per block, one wave)
    recur_kernel<<<BB * HH / 2, 512>>>(proj, term, tkp, tvp, sprev, tick, attn);

    // 3) Output projection: out = attn @ Wo^T + bo  (8192 x 512)
    {
        dim3 grid(DD / GBN, MM / GBM);
        mma_gemm<<<grid, 256>>>(attn, wo, (float*)d_out, MM, DD, DD, bo);
    }
}

// round 5
// speedup vs baseline: 1.1278x; 1.1278x over previous
#include <cuda_runtime.h>
#include <math.h>
#include <stdint.h>

// Problem constants
#define TT   256
#define BB   32
#define DD   512
#define HH   8
#define HDd  64
#define ETA  4
#define RR   4
#define FEAT 256
#define MM   (TT*BB)        // 8192
#define NPROJ2 2688         // 5*H*HD + 3*H*ETA + 32 pad  (21*128)
#define WROWS  2560         // 5*H*HD

// Scratch (device globals; allocation-free per harness rules)
__device__ float g_x   [(size_t)MM * DD];        // tf32-rounded inputs
__device__ float g_w5  [(size_t)NPROJ2 * DD];    // tf32 Wq|Wk|Wv|Wb|Wg|Wp1|Wp2|Wp3|0
__device__ float g_wo  [(size_t)DD * DD];        // tf32-rounded Wo
__device__ float g_proj[(size_t)MM * NPROJ2];
__device__ float g_attn[(size_t)MM * DD];        // tf32-rounded attn

__device__ __forceinline__ float tf32r(float x) {
    float r;
    asm("cvt.rna.tf32.f32 %0, %1;" : "=f"(r) : "f"(x));
    return r;
}

__global__ void cvt1_kernel(float* __restrict__ dst, const float* __restrict__ src, int n) {
    int i = blockIdx.x * 256 + threadIdx.x;
    if (i < n) dst[i] = tf32r(src[i]);
}
__global__ void cvt5_kernel(float* __restrict__ dst,
                            const float* __restrict__ s0, const float* __restrict__ s1,
                            const float* __restrict__ s2, const float* __restrict__ s3,
                            const float* __restrict__ s4, int per) {
    int i = blockIdx.x * 256 + threadIdx.x;
    if (i >= 5 * per) return;
    int seg = i / per, j = i - seg * per;
    const float* s = (seg == 0) ? s0 : (seg == 1) ? s1 : (seg == 2) ? s2 : (seg == 3) ? s3 : s4;
    dst[i] = tf32r(s[j]);
}
__global__ void cvtp_kernel(float* __restrict__ dst,   // dst = g_w5 + WROWS*DD
                            const float* __restrict__ s0, const float* __restrict__ s1,
                            const float* __restrict__ s2, int per) {
    int i = blockIdx.x * 256 + threadIdx.x;
    if (i >= 4 * per) return;
    int seg = i / per, j = i - seg * per;
    float v = 0.f;
    if (seg == 0) v = tf32r(s0[j]);
    else if (seg == 1) v = tf32r(s1[j]);
    else if (seg == 2) v = tf32r(s2[j]);
    dst[i] = v;
}

// ---------------------------------------------------------------------------
// TF32 tensor-core GEMM: C[M x N] = A[M x K] @ B[N x K]^T (+bias)
// 3-stage cp.async pipeline, one __syncthreads per K-iter.
// ---------------------------------------------------------------------------
#define GBM 128
#define GBN 128
#define GBK 16
#define KPAD 20
#define STG 3

__global__ __launch_bounds__(256) void mma_gemm(
    const float* __restrict__ A, const float* __restrict__ B,
    float* __restrict__ C, int M, int N, int K, const float* __restrict__ bias)
{
    __shared__ float As[STG][GBM * KPAD];
    __shared__ float Bs[STG][GBN * KPAD];

    const int tid  = threadIdx.x;
    const int lane = tid & 31;
    const int wid  = tid >> 5;
    const int wm   = wid & 1;
    const int wn   = wid >> 1;
    const int m0   = blockIdx.y * GBM;
    const int n0   = blockIdx.x * GBN;

    const unsigned asbase = (unsigned)__cvta_generic_to_shared(&As[0][0]);
    const unsigned bsbase = (unsigned)__cvta_generic_to_shared(&Bs[0][0]);

    const int a_r  = lane & 15;
    const int a_k4 = (lane >> 4) * 4;
    const int b_n  = lane & 7;
    const int b_k4 = (lane >> 3) * 4;

    float acc[4][4][4];
#pragma unroll
    for (int i = 0; i < 4; i++)
#pragma unroll
        for (int j = 0; j < 4; j++)
#pragma unroll
            for (int c = 0; c < 4; c++) acc[i][j][c] = 0.f;

    auto prefetch = [&](int it, int buf) {
        const int k0 = it * GBK;
#pragma unroll
        for (int i = 0; i < 2; i++) {
            int idx = tid + i * 256;
            int r   = idx >> 2;
            int k4  = (idx & 3) * 4;
            unsigned da = asbase + (unsigned)((buf * GBM * KPAD + r * KPAD + k4) * 4);
            const float* sa = A + (size_t)(m0 + r) * K + k0 + k4;
            asm volatile("cp.async.ca.shared.global [%0], [%1], 16;\n" :: "r"(da), "l"(sa));
            unsigned db = bsbase + (unsigned)((buf * GBN * KPAD + r * KPAD + k4) * 4);
            const float* sb = B + (size_t)(n0 + r) * K + k0 + k4;
            asm volatile("cp.async.ca.shared.global [%0], [%1], 16;\n" :: "r"(db), "l"(sb));
        }
        asm volatile("cp.async.commit_group;\n");
    };

    const int NIT = K / GBK;
    prefetch(0, 0);
    if (NIT > 1) prefetch(1, 1);

    int buf = 0, pf = 2;
    for (int it = 0; it < NIT; ++it) {
        if (it + 1 < NIT) {
            asm volatile("cp.async.wait_group 1;\n");
        } else {
            asm volatile("cp.async.wait_group 0;\n");
        }
        __syncthreads();   // single barrier per iter (stage ring distance 3)

        uint32_t bf[4][4];
#pragma unroll
        for (int nt = 0; nt < 4; nt++) {
            unsigned addr = bsbase + (unsigned)((buf * GBN * KPAD +
                            (wn * 32 + nt * 8 + b_n) * KPAD + b_k4) * 4);
            asm volatile("ldmatrix.sync.aligned.m8n8.x4.shared.b16 {%0,%1,%2,%3}, [%4];"
                : "=r"(bf[nt][0]), "=r"(bf[nt][1]), "=r"(bf[nt][2]), "=r"(bf[nt][3])
                : "r"(addr));
        }

#pragma unroll
        for (int k8 = 0; k8 < 2; k8++) {
            uint32_t af[4][4];
#pragma unroll
            for (int mt = 0; mt < 4; mt++) {
                unsigned addr = asbase + (unsigned)((buf * GBM * KPAD +
                                (wm * 64 + mt * 16 + a_r) * KPAD + k8 * 8 + a_k4) * 4);
                asm volatile("ldmatrix.sync.aligned.m8n8.x4.shared.b16 {%0,%1,%2,%3}, [%4];"
                    : "=r"(af[mt][0]), "=r"(af[mt][1]), "=r"(af[mt][2]), "=r"(af[mt][3])
                    : "r"(addr));
            }
#pragma unroll
            for (int mt = 0; mt < 4; mt++)
#pragma unroll
                for (int nt = 0; nt < 4; nt++) {
                    asm volatile(
                        "mma.sync.aligned.m16n8k8.row.col.f32.tf32.tf32.f32 "
                        "{%0,%1,%2,%3}, {%4,%5,%6,%7}, {%8,%9}, {%0,%1,%2,%3};"
                        : "+f"(acc[mt][nt][0]), "+f"(acc[mt][nt][1]),
                          "+f"(acc[mt][nt][2]), "+f"(acc[mt][nt][3])
                        : "r"(af[mt][0]), "r"(af[mt][1]), "r"(af[mt][2]), "r"(af[mt][3]),
                          "r"(bf[nt][k8 * 2]), "r"(bf[nt][k8 * 2 + 1]));
                }
        }

        if (it + 2 < NIT) prefetch(it + 2, pf);
        buf = (buf + 1 == STG) ? 0 : buf + 1;
        pf  = (pf  + 1 == STG) ? 0 : pf + 1;
    }

#pragma unroll
    for (int mt = 0; mt < 4; mt++) {
        int row = m0 + wm * 64 + mt * 16 + (lane >> 2);
#pragma unroll
        for (int nt = 0; nt < 4; nt++) {
            int col = n0 + wn * 32 + nt * 8 + (lane & 3) * 2;
            float b0v = bias ? bias[col]     : 0.f;
            float b1v = bias ? bias[col + 1] : 0.f;
            float2 v0 = make_float2(acc[mt][nt][0] + b0v, acc[mt][nt][1] + b1v);
            float2 v1 = make_float2(acc[mt][nt][2] + b0v, acc[mt][nt][3] + b1v);
            *reinterpret_cast<float2*>(&C[(size_t)row * N + col]) = v0;
            *reinterpret_cast<float2*>(&C[(size_t)(row + 8) * N + col]) = v1;
        }
    }
}

// ---------------------------------------------------------------------------
// Recurrence kernel v4: 256 threads per block, one block per (b,h),
// 4-buffer cp.async staging with prefetch distance 3 (covers DRAM latency).
// ---------------------------------------------------------------------------
__device__ __forceinline__ float sigf(float x) {
    return 1.f / (1.f + __expf(-x));
}

#define NBUF 4

__global__ __launch_bounds__(256) void recur_kernel(
    const float* __restrict__ proj,   // [MM][2688] q|k|v|b|g|p1|p2|p3
    const int*   __restrict__ term,   // [MM]
    const float* __restrict__ tkp,    // (B,R,H,FEAT)
    const float* __restrict__ tvp,    // (B,R,H,HD)
    const float* __restrict__ sprev,  // (B,H,FEAT)
    const float* __restrict__ tick,   // (B,)
    float* __restrict__ attn)         // [MM][512], tf32-rounded on write
{
    const int bh = blockIdx.x;
    const int b = bh >> 3;
    const int h = bh & 7;
    const int tid = threadIdx.x;
    const int e = tid >> 6;
    const int d = tid & 63;

    __shared__ __align__(16) float sstage[NBUF][5][64];
    __shared__ __align__(16) float sp[NBUF][3][4];
    __shared__ int sterm[NBUF];
    __shared__ float red[5][8];
    __shared__ float kvbuf[256];

    float ks0 = tkp[((size_t)(b * RR + 0) * HH + h) * FEAT + tid];
    float ks1 = tkp[((size_t)(b * RR + 1) * HH + h) * FEAT + tid];
    float ks2 = tkp[((size_t)(b * RR + 2) * HH + h) * FEAT + tid];
    float ks3 = tkp[((size_t)(b * RR + 3) * HH + h) * FEAT + tid];
    float vs  = tvp[((size_t)(b * RR + e) * HH + h) * HDd + d];
    float ss  = sprev[((size_t)(b * HH + h)) * FEAT + tid];

    const float PI = 3.14159265358979323846f;
    const float tk = tick[b];

    float cr0, cr1, cr2, cr3, sr0, sr1, sr2, sr3;
    float cw0, cw1, cw2, cw3, sw0, sw1, sw2, sw3;
    {
        float om0 = -PI;
        float om1 = -PI + 2.f * PI / 3.f;
        float om2 = -PI + 4.f * PI / 3.f;
        float om3 = PI;
        float a;
        a = (1.f + tk) * om0; cr0 = cosf(a); sr0 = sinf(a);
        a = (1.f + tk) * om1; cr1 = cosf(a); sr1 = sinf(a);
        a = (1.f + tk) * om2; cr2 = cosf(a); sr2 = sinf(a);
        a = (1.f + tk) * om3; cr3 = cosf(a); sr3 = sinf(a);
        cw0 = cosf(om0); sw0 = sinf(om0);
        cw1 = cosf(om1); sw1 = sinf(om1);
        cw2 = cosf(om2); sw2 = sinf(om2);
        cw3 = cosf(om3); sw3 = sinf(om3);
    }

    // Async stage of step t's operands into buffer `buf`; one commit group each.
    auto stage = [&](int t, int buf) {
        const int m = t * BB + b;
        if (tid < 80) {
            const int seg = tid >> 4;
            const int j = (tid & 15) * 4;
            const float* src = proj + (size_t)m * NPROJ2 + seg * 512 + h * HDd + j;
            unsigned dst = (unsigned)__cvta_generic_to_shared(&sstage[buf][seg][j]);
            asm volatile("cp.async.ca.shared.global [%0], [%1], 16;\n" :: "r"(dst), "l"(src));
        } else if (tid < 83) {
            const int j = tid - 80;
            const float* src = proj + (size_t)m * NPROJ2 + WROWS + j * 32 + h * ETA;
            unsigned dst = (unsigned)__cvta_generic_to_shared(&sp[buf][j][0]);
            asm volatile("cp.async.ca.shared.global [%0], [%1], 16;\n" :: "r"(dst), "l"(src));
        } else if (tid == 83) {
            const int* src = term + m;
            unsigned dst = (unsigned)__cvta_generic_to_shared(&sterm[buf]);
            asm volatile("cp.async.ca.shared.global [%0], [%1], 4;\n" :: "r"(dst), "l"(src));
        }
        asm volatile("cp.async.commit_group;\n");
    };

    stage(0, 0);
    stage(1, 1);
    stage(2, 2);

    for (int t = 0; t < TT; t++) {
        const int buf = t & (NBUF - 1);
        // Prefetch t+3 (overwrites buffer of t-1, fully consumed by barrier S2 of t-1)
        if (t + 3 < TT) {
            stage(t + 3, (t + 3) & (NBUF - 1));
            asm volatile("cp.async.wait_group 3;\n");
        } else if (t + 2 < TT) {
            asm volatile("cp.async.wait_group 2;\n");
        } else if (t + 1 < TT) {
            asm volatile("cp.async.wait_group 1;\n");
        } else {
            asm volatile("cp.async.wait_group 0;\n");
        }
        __syncthreads();   // S1: buffer `buf` visible to all

        const float qd = sstage[buf][0][d];
        const float kd = sstage[buf][1][d];
        const float vv = sstage[buf][2][d];
        const float bd = sigf(sstage[buf][3][d]);
        const float gd = sigf(sstage[buf][4][d]);
        const float p1e = sp[buf][0][e];
        const float p2e = sp[buf][1][e];
        const float p3e = sigf(sp[buf][2][e]);
        const float tf = 1.f - (float)sterm[buf];

        const float phi = fmaxf(qd * p2e, 0.f);
        const float psi = fmaxf(kd * p1e, 0.f);
        const float gf  = gd * p3e;
        const float gk  = psi * gf;
        const float dg  = (1.f - gf) * tf;

        ss = dg * ss + gk;
        float v4 = ss * phi;

        ks0 = dg * ks0 + gk * cr0;
        ks1 = dg * ks1 + gk * cr1;
        ks2 = dg * ks2 + gk * cr2;
        ks3 = dg * ks3 + gk * cr3;
        float v0 = ks0 * phi;
        float v1 = ks1 * phi;
        float v2 = ks2 * phi;
        float v3 = ks3 * phi;

        const float ce = (e == 0) ? cr0 : (e == 1) ? cr1 : (e == 2) ? cr2 : cr3;
        vs = (1.f - bd) * tf * vs + (vv * bd) * ce;

#pragma unroll
        for (int o = 16; o > 0; o >>= 1) {
            v0 += __shfl_down_sync(0xffffffffu, v0, o);
            v1 += __shfl_down_sync(0xffffffffu, v1, o);
            v2 += __shfl_down_sync(0xffffffffu, v2, o);
            v3 += __shfl_down_sync(0xffffffffu, v3, o);
            v4 += __shfl_down_sync(0xffffffffu, v4, o);
        }
        const int warp = tid >> 5;
        if ((tid & 31) == 0) {
            red[0][warp] = v0;
            red[1][warp] = v1;
            red[2][warp] = v2;
            red[3][warp] = v3;
            red[4][warp] = v4;
        }
        __syncthreads();   // S2: per-warp partials visible (also: buf fully read)

        float kdq_e = 0.f, norm = 0.f;
#pragma unroll
        for (int w = 0; w < 8; w++) {
            kdq_e += red[e][w];
            norm  += red[4][w];
        }

        kvbuf[tid] = vs * kdq_e;
        __syncthreads();   // S3: kvbuf visible

        if (tid < 64) {
            const int m = t * BB + b;
            float kv = kvbuf[tid] + kvbuf[tid + 64] + kvbuf[tid + 128] + kvbuf[tid + 192];
            attn[(size_t)m * DD + h * HDd + tid] = tf32r(kv / (8.f * norm + 1e-6f));
        }

        float c2, s2;
        c2 = cr0 * cw0 - sr0 * sw0; s2 = sr0 * cw0 + cr0 * sw0; cr0 = c2; sr0 = s2;
        c2 = cr1 * cw1 - sr1 * sw1; s2 = sr1 * cw1 + cr1 * sw1; cr1 = c2; sr1 = s2;
        c2 = cr2 * cw2 - sr2 * sw2; s2 = sr2 * cw2 + cr2 * sw2; cr2 = c2; sr2 = s2;
        c2 = cr3 * cw3 - sr3 * sw3; s2 = sr3 * cw3 + cr3 * sw3; cr3 = c2; sr3 = s2;
    }
}

// ---------------------------------------------------------------------------
extern "C" void kernel_launch(void* const* d_in, const int* in_sizes, int n_in,
                              void* d_out, int out_size)
{
    const float* inputs = (const float*)d_in[0];
    const int*   term   = (const int*)d_in[1];
    const float* tkp    = (const float*)d_in[2];
    const float* tvp    = (const float*)d_in[3];
    const float* sprev  = (const float*)d_in[4];
    const float* tick   = (const float*)d_in[5];
    const float* Wq     = (const float*)d_in[6];
    const float* Wk     = (const float*)d_in[7];
    const float* Wv     = (const float*)d_in[8];
    const float* Wb     = (const float*)d_in[9];
    const float* Wg     = (const float*)d_in[10];
    const float* Wp1    = (const float*)d_in[11];
    const float* Wp2    = (const float*)d_in[12];
    const float* Wp3    = (const float*)d_in[13];
    const float* Wo     = (const float*)d_in[14];
    const float* bo     = (const float*)d_in[15];

    void* p;
    cudaGetSymbolAddress(&p, g_x);    float* x    = (float*)p;
    cudaGetSymbolAddress(&p, g_w5);   float* w5   = (float*)p;
    cudaGetSymbolAddress(&p, g_wo);   float* wo   = (float*)p;
    cudaGetSymbolAddress(&p, g_proj); float* proj = (float*)p;
    cudaGetSymbolAddress(&p, g_attn); float* attn = (float*)p;

    const int WSZ = HH * HDd * DD;    // 262144
    const int PSZ = HH * ETA * DD;    // 16384

    cvt1_kernel<<<(MM * DD + 255) / 256, 256>>>(x, inputs, MM * DD);
    cvt5_kernel<<<(5 * WSZ + 255) / 256, 256>>>(w5, Wq, Wk, Wv, Wb, Wg, WSZ);
    cvtp_kernel<<<(4 * PSZ + 255) / 256, 256>>>(w5 + (size_t)WROWS * DD, Wp1, Wp2, Wp3, PSZ);
    cvt1_kernel<<<(WSZ + 255) / 256, 256>>>(wo, Wo, WSZ);

    // 1) Fused projection: (8192 x 2688) — q,k,v,beta,gamma,p1,p2,p3
    {
        dim3 grid(NPROJ2 / GBN, MM / GBM);
        mma_gemm<<<grid, 256>>>(x, w5, proj, MM, NPROJ2, DD, nullptr);
    }
    // 2) Recurrence (one block per (b,h), 4-deep pipeline)
    recur_kernel<<<BB * HH, 256>>>(proj, term, tkp, tvp, sprev, tick, attn);

    // 3) Output projection: out = attn @ Wo^T + bo  (8192 x 512)
    {
        dim3 grid(DD / GBN, MM / GBM);
        mma_gemm<<<grid, 256>>>(attn, wo, (float*)d_out, MM, DD, DD, bo);
    }
}

// round 6
// speedup vs baseline: 1.2334x; 1.0936x over previous
#include <cuda_runtime.h>
#include <math.h>
#include <stdint.h>

// Problem constants
#define TT   256
#define BB   32
#define DD   512
#define HH   8
#define HDd  64
#define ETA  4
#define RR   4
#define FEAT 256
#define MM   (TT*BB)        // 8192
#define NPROJ2 2688         // 5*H*HD + 3*H*ETA + 32 pad  (21*128)
#define WROWS  2560         // 5*H*HD

// Scratch (device globals; allocation-free per harness rules)
__device__ float g_x   [(size_t)MM * DD];        // tf32-rounded inputs
__device__ float g_w5  [(size_t)NPROJ2 * DD];    // tf32 Wq|Wk|Wv|Wb|Wg|Wp1|Wp2|Wp3|0
__device__ float g_wo  [(size_t)DD * DD];        // tf32-rounded Wo
__device__ float g_proj[(size_t)MM * NPROJ2];
__device__ float g_attn[(size_t)MM * DD];        // tf32-rounded attn

__device__ __forceinline__ float tf32r(float x) {
    float r;
    asm("cvt.rna.tf32.f32 %0, %1;" : "=f"(r) : "f"(x));
    return r;
}

__global__ void cvt1_kernel(float* __restrict__ dst, const float* __restrict__ src, int n) {
    int i = blockIdx.x * 256 + threadIdx.x;
    if (i < n) dst[i] = tf32r(src[i]);
}
__global__ void cvt5_kernel(float* __restrict__ dst,
                            const float* __restrict__ s0, const float* __restrict__ s1,
                            const float* __restrict__ s2, const float* __restrict__ s3,
                            const float* __restrict__ s4, int per) {
    int i = blockIdx.x * 256 + threadIdx.x;
    if (i >= 5 * per) return;
    int seg = i / per, j = i - seg * per;
    const float* s = (seg == 0) ? s0 : (seg == 1) ? s1 : (seg == 2) ? s2 : (seg == 3) ? s3 : s4;
    dst[i] = tf32r(s[j]);
}
__global__ void cvtp_kernel(float* __restrict__ dst,   // dst = g_w5 + WROWS*DD
                            const float* __restrict__ s0, const float* __restrict__ s1,
                            const float* __restrict__ s2, int per) {
    int i = blockIdx.x * 256 + threadIdx.x;
    if (i >= 4 * per) return;
    int seg = i / per, j = i - seg * per;
    float v = 0.f;
    if (seg == 0) v = tf32r(s0[j]);
    else if (seg == 1) v = tf32r(s1[j]);
    else if (seg == 2) v = tf32r(s2[j]);
    dst[i] = v;
}

// ---------------------------------------------------------------------------
// TF32 tensor-core GEMM: C[M x N] = A[M x K] @ B[N x K]^T (+bias)
// 3-stage cp.async pipeline, one __syncthreads per K-iter. (unchanged)
// ---------------------------------------------------------------------------
#define GBM 128
#define GBN 128
#define GBK 16
#define KPAD 20
#define STG 3

__global__ __launch_bounds__(256) void mma_gemm(
    const float* __restrict__ A, const float* __restrict__ B,
    float* __restrict__ C, int M, int N, int K, const float* __restrict__ bias)
{
    __shared__ float As[STG][GBM * KPAD];
    __shared__ float Bs[STG][GBN * KPAD];

    const int tid  = threadIdx.x;
    const int lane = tid & 31;
    const int wid  = tid >> 5;
    const int wm   = wid & 1;
    const int wn   = wid >> 1;
    const int m0   = blockIdx.y * GBM;
    const int n0   = blockIdx.x * GBN;

    const unsigned asbase = (unsigned)__cvta_generic_to_shared(&As[0][0]);
    const unsigned bsbase = (unsigned)__cvta_generic_to_shared(&Bs[0][0]);

    const int a_r  = lane & 15;
    const int a_k4 = (lane >> 4) * 4;
    const int b_n  = lane & 7;
    const int b_k4 = (lane >> 3) * 4;

    float acc[4][4][4];
#pragma unroll
    for (int i = 0; i < 4; i++)
#pragma unroll
        for (int j = 0; j < 4; j++)
#pragma unroll
            for (int c = 0; c < 4; c++) acc[i][j][c] = 0.f;

    auto prefetch = [&](int it, int buf) {
        const int k0 = it * GBK;
#pragma unroll
        for (int i = 0; i < 2; i++) {
            int idx = tid + i * 256;
            int r   = idx >> 2;
            int k4  = (idx & 3) * 4;
            unsigned da = asbase + (unsigned)((buf * GBM * KPAD + r * KPAD + k4) * 4);
            const float* sa = A + (size_t)(m0 + r) * K + k0 + k4;
            asm volatile("cp.async.ca.shared.global [%0], [%1], 16;\n" :: "r"(da), "l"(sa));
            unsigned db = bsbase + (unsigned)((buf * GBN * KPAD + r * KPAD + k4) * 4);
            const float* sb = B + (size_t)(n0 + r) * K + k0 + k4;
            asm volatile("cp.async.ca.shared.global [%0], [%1], 16;\n" :: "r"(db), "l"(sb));
        }
        asm volatile("cp.async.commit_group;\n");
    };

    const int NIT = K / GBK;
    prefetch(0, 0);
    if (NIT > 1) prefetch(1, 1);

    int buf = 0, pf = 2;
    for (int it = 0; it < NIT; ++it) {
        if (it + 1 < NIT) {
            asm volatile("cp.async.wait_group 1;\n");
        } else {
            asm volatile("cp.async.wait_group 0;\n");
        }
        __syncthreads();

        uint32_t bf[4][4];
#pragma unroll
        for (int nt = 0; nt < 4; nt++) {
            unsigned addr = bsbase + (unsigned)((buf * GBN * KPAD +
                            (wn * 32 + nt * 8 + b_n) * KPAD + b_k4) * 4);
            asm volatile("ldmatrix.sync.aligned.m8n8.x4.shared.b16 {%0,%1,%2,%3}, [%4];"
                : "=r"(bf[nt][0]), "=r"(bf[nt][1]), "=r"(bf[nt][2]), "=r"(bf[nt][3])
                : "r"(addr));
        }

#pragma unroll
        for (int k8 = 0; k8 < 2; k8++) {
            uint32_t af[4][4];
#pragma unroll
            for (int mt = 0; mt < 4; mt++) {
                unsigned addr = asbase + (unsigned)((buf * GBM * KPAD +
                                (wm * 64 + mt * 16 + a_r) * KPAD + k8 * 8 + a_k4) * 4);
                asm volatile("ldmatrix.sync.aligned.m8n8.x4.shared.b16 {%0,%1,%2,%3}, [%4];"
                    : "=r"(af[mt][0]), "=r"(af[mt][1]), "=r"(af[mt][2]), "=r"(af[mt][3])
                    : "r"(addr));
            }
#pragma unroll
            for (int mt = 0; mt < 4; mt++)
#pragma unroll
                for (int nt = 0; nt < 4; nt++) {
                    asm volatile(
                        "mma.sync.aligned.m16n8k8.row.col.f32.tf32.tf32.f32 "
                        "{%0,%1,%2,%3}, {%4,%5,%6,%7}, {%8,%9}, {%0,%1,%2,%3};"
                        : "+f"(acc[mt][nt][0]), "+f"(acc[mt][nt][1]),
                          "+f"(acc[mt][nt][2]), "+f"(acc[mt][nt][3])
                        : "r"(af[mt][0]), "r"(af[mt][1]), "r"(af[mt][2]), "r"(af[mt][3]),
                          "r"(bf[nt][k8 * 2]), "r"(bf[nt][k8 * 2 + 1]));
                }
        }

        if (it + 2 < NIT) prefetch(it + 2, pf);
        buf = (buf + 1 == STG) ? 0 : buf + 1;
        pf  = (pf  + 1 == STG) ? 0 : pf + 1;
    }

#pragma unroll
    for (int mt = 0; mt < 4; mt++) {
        int row = m0 + wm * 64 + mt * 16 + (lane >> 2);
#pragma unroll
        for (int nt = 0; nt < 4; nt++) {
            int col = n0 + wn * 32 + nt * 8 + (lane & 3) * 2;
            float b0v = bias ? bias[col]     : 0.f;
            float b1v = bias ? bias[col + 1] : 0.f;
            float2 v0 = make_float2(acc[mt][nt][0] + b0v, acc[mt][nt][1] + b1v);
            float2 v1 = make_float2(acc[mt][nt][2] + b0v, acc[mt][nt][3] + b1v);
            *reinterpret_cast<float2*>(&C[(size_t)row * N + col]) = v0;
            *reinterpret_cast<float2*>(&C[(size_t)(row + 8) * N + col]) = v1;
        }
    }
}

// ---------------------------------------------------------------------------
// Recurrence kernel v5: 64 threads per (b,h); thread d owns all 4 eta-slices
// and all 4 r-slices. ONE __syncthreads per timestep (publishes both the
// reduction partials of step t and the cp.async stage for step t+1).
// ---------------------------------------------------------------------------
__device__ __forceinline__ float sigf(float x) {
    return 1.f / (1.f + __expf(-x));
}

#define NBUF 4

__global__ __launch_bounds__(64) void recur_kernel(
    const float* __restrict__ proj,   // [MM][2688] q|k|v|b|g|p1|p2|p3
    const int*   __restrict__ term,   // [MM]
    const float* __restrict__ tkp,    // (B,R,H,FEAT)
    const float* __restrict__ tvp,    // (B,R,H,HD)
    const float* __restrict__ sprev,  // (B,H,FEAT)
    const float* __restrict__ tick,   // (B,)
    float* __restrict__ attn)         // [MM][512], tf32-rounded on write
{
    const int bh = blockIdx.x;
    const int b = bh >> 3;
    const int h = bh & 7;
    const int d = threadIdx.x;        // 0..63

    __shared__ __align__(16) float sstage[NBUF][5][64];  // q,k,v,b_raw,g_raw
    __shared__ __align__(16) float sp[NBUF][3][4];       // p1,p2,p3_raw
    __shared__ int sterm[NBUF];
    __shared__ float red[2][5][2];                       // [t&1][value][warp]

    // Per-thread state: ks[e][r], ss[e], vs[r]
    float ks[4][4], ss[4], vs[4];
#pragma unroll
    for (int e = 0; e < 4; e++) {
#pragma unroll
        for (int r = 0; r < 4; r++)
            ks[e][r] = tkp[((size_t)(b * RR + r) * HH + h) * FEAT + e * 64 + d];
        ss[e] = sprev[((size_t)(b * HH + h)) * FEAT + e * 64 + d];
    }
#pragma unroll
    for (int r = 0; r < 4; r++)
        vs[r] = tvp[((size_t)(b * RR + r) * HH + h) * HDd + d];

    const float PI = 3.14159265358979323846f;
    const float tk = tick[b];

    float cr0, cr1, cr2, cr3, sr0, sr1, sr2, sr3;
    float cw0, cw1, cw2, cw3, sw0, sw1, sw2, sw3;
    {
        float om0 = -PI;
        float om1 = -PI + 2.f * PI / 3.f;
        float om2 = -PI + 4.f * PI / 3.f;
        float om3 = PI;
        float a;
        a = (1.f + tk) * om0; cr0 = cosf(a); sr0 = sinf(a);
        a = (1.f + tk) * om1; cr1 = cosf(a); sr1 = sinf(a);
        a = (1.f + tk) * om2; cr2 = cosf(a); sr2 = sinf(a);
        a = (1.f + tk) * om3; cr3 = cosf(a); sr3 = sinf(a);
        cw0 = cosf(om0); sw0 = sinf(om0);
        cw1 = cosf(om1); sw1 = sinf(om1);
        cw2 = cosf(om2); sw2 = sinf(om2);
        cw3 = cosf(om3); sw3 = sinf(om3);
    }

    // Stage step t's operands into buffer `buf` (one commit group).
    auto stage = [&](int t, int buf) {
        const int m = t * BB + b;
        {
            const int seg = d >> 4;            // 0..3
            const int j = (d & 15) * 4;
            const float* src = proj + (size_t)m * NPROJ2 + seg * 512 + h * HDd + j;
            unsigned dst = (unsigned)__cvta_generic_to_shared(&sstage[buf][seg][j]);
            asm volatile("cp.async.ca.shared.global [%0], [%1], 16;\n" :: "r"(dst), "l"(src));
        }
        if (d < 16) {                          // seg 4 (gamma)
            const float* src = proj + (size_t)m * NPROJ2 + 4 * 512 + h * HDd + d * 4;
            unsigned dst = (unsigned)__cvta_generic_to_shared(&sstage[buf][4][d * 4]);
            asm volatile("cp.async.ca.shared.global [%0], [%1], 16;\n" :: "r"(dst), "l"(src));
        } else if (d < 19) {                   // p1,p2,p3
            const int j = d - 16;
            const float* src = proj + (size_t)m * NPROJ2 + WROWS + j * 32 + h * ETA;
            unsigned dst = (unsigned)__cvta_generic_to_shared(&sp[buf][j][0]);
            asm volatile("cp.async.ca.shared.global [%0], [%1], 16;\n" :: "r"(dst), "l"(src));
        } else if (d == 19) {
            const int* src = term + m;
            unsigned dst = (unsigned)__cvta_generic_to_shared(&sterm[buf]);
            asm volatile("cp.async.ca.shared.global [%0], [%1], 4;\n" :: "r"(dst), "l"(src));
        }
        asm volatile("cp.async.commit_group;\n");
    };

    stage(0, 0);
    stage(1, 1);
    stage(2, 2);
    asm volatile("cp.async.wait_group 2;\n");   // buffer 0 complete
    __syncthreads();                            // buffer 0 visible

    const int warp = d >> 5;

    for (int t = 0; t < TT; t++) {
        const int buf = t & (NBUF - 1);

        const float qd   = sstage[buf][0][d];
        const float kd   = sstage[buf][1][d];
        const float vv   = sstage[buf][2][d];
        const float bd   = sigf(sstage[buf][3][d]);
        const float gd   = sigf(sstage[buf][4][d]);
        const float tf   = 1.f - (float)sterm[buf];

        float v0 = 0.f, v1 = 0.f, v2 = 0.f, v3 = 0.f, v4 = 0.f;
#pragma unroll
        for (int e = 0; e < 4; e++) {
            const float phi = fmaxf(qd * sp[buf][1][e], 0.f);
            const float psi = fmaxf(kd * sp[buf][0][e], 0.f);
            const float gf  = gd * sigf(sp[buf][2][e]);
            const float gk  = psi * gf;
            const float dg  = (1.f - gf) * tf;

            ss[e] = dg * ss[e] + gk;
            v4 += ss[e] * phi;

            ks[e][0] = dg * ks[e][0] + gk * cr0;  v0 += ks[e][0] * phi;
            ks[e][1] = dg * ks[e][1] + gk * cr1;  v1 += ks[e][1] * phi;
            ks[e][2] = dg * ks[e][2] + gk * cr2;  v2 += ks[e][2] * phi;
            ks[e][3] = dg * ks[e][3] + gk * cr3;  v3 += ks[e][3] * phi;
        }

        // V-state (all 4 r owned locally)
        const float bv = vv * bd;
        const float om = (1.f - bd) * tf;
        vs[0] = om * vs[0] + bv * cr0;
        vs[1] = om * vs[1] + bv * cr1;
        vs[2] = om * vs[2] + bv * cr2;
        vs[3] = om * vs[3] + bv * cr3;

        // Warp butterfly (all lanes end with warp total)
#pragma unroll
        for (int o = 16; o > 0; o >>= 1) {
            v0 += __shfl_xor_sync(0xffffffffu, v0, o);
            v1 += __shfl_xor_sync(0xffffffffu, v1, o);
            v2 += __shfl_xor_sync(0xffffffffu, v2, o);
            v3 += __shfl_xor_sync(0xffffffffu, v3, o);
            v4 += __shfl_xor_sync(0xffffffffu, v4, o);
        }
        const int pb = t & 1;
        if ((d & 31) == 0) {
            red[pb][0][warp] = v0;
            red[pb][1][warp] = v1;
            red[pb][2][warp] = v2;
            red[pb][3][warp] = v3;
            red[pb][4][warp] = v4;
        }

        // Prefetch step t+3, then ensure t+1's group is done, then the single
        // barrier publishes BOTH the reduction partials and buffer t+1.
        if (t + 3 < TT) {
            stage(t + 3, (t + 3) & (NBUF - 1));
            asm volatile("cp.async.wait_group 2;\n");
        } else if (t + 2 < TT) {
            asm volatile("cp.async.wait_group 1;\n");
        } else {
            asm volatile("cp.async.wait_group 0;\n");
        }
        __syncthreads();

        const float kdq0 = red[pb][0][0] + red[pb][0][1];
        const float kdq1 = red[pb][1][0] + red[pb][1][1];
        const float kdq2 = red[pb][2][0] + red[pb][2][1];
        const float kdq3 = red[pb][3][0] + red[pb][3][1];
        const float norm = red[pb][4][0] + red[pb][4][1];

        const float kv = vs[0] * kdq0 + vs[1] * kdq1 + vs[2] * kdq2 + vs[3] * kdq3;
        const int m = t * BB + b;
        attn[(size_t)m * DD + h * HDd + d] = tf32r(kv / (8.f * norm + 1e-6f));

        float c2, s2;
        c2 = cr0 * cw0 - sr0 * sw0; s2 = sr0 * cw0 + cr0 * sw0; cr0 = c2; sr0 = s2;
        c2 = cr1 * cw1 - sr1 * sw1; s2 = sr1 * cw1 + cr1 * sw1; cr1 = c2; sr1 = s2;
        c2 = cr2 * cw2 - sr2 * sw2; s2 = sr2 * cw2 + cr2 * sw2; cr2 = c2; sr2 = s2;
        c2 = cr3 * cw3 - sr3 * sw3; s2 = sr3 * cw3 + cr3 * sw3; cr3 = c2; sr3 = s2;
    }
}

// ---------------------------------------------------------------------------
extern "C" void kernel_launch(void* const* d_in, const int* in_sizes, int n_in,
                              void* d_out, int out_size)
{
    const float* inputs = (const float*)d_in[0];
    const int*   term   = (const int*)d_in[1];
    const float* tkp    = (const float*)d_in[2];
    const float* tvp    = (const float*)d_in[3];
    const float* sprev  = (const float*)d_in[4];
    const float* tick   = (const float*)d_in[5];
    const float* Wq     = (const float*)d_in[6];
    const float* Wk     = (const float*)d_in[7];
    const float* Wv     = (const float*)d_in[8];
    const float* Wb     = (const float*)d_in[9];
    const float* Wg     = (const float*)d_in[10];
    const float* Wp1    = (const float*)d_in[11];
    const float* Wp2    = (const float*)d_in[12];
    const float* Wp3    = (const float*)d_in[13];
    const float* Wo     = (const float*)d_in[14];
    const float* bo     = (const float*)d_in[15];

    void* p;
    cudaGetSymbolAddress(&p, g_x);    float* x    = (float*)p;
    cudaGetSymbolAddress(&p, g_w5);   float* w5   = (float*)p;
    cudaGetSymbolAddress(&p, g_wo);   float* wo   = (float*)p;
    cudaGetSymbolAddress(&p, g_proj); float* proj = (float*)p;
    cudaGetSymbolAddress(&p, g_attn); float* attn = (float*)p;

    const int WSZ = HH * HDd * DD;    // 262144
    const int PSZ = HH * ETA * DD;    // 16384

    cvt1_kernel<<<(MM * DD + 255) / 256, 256>>>(x, inputs, MM * DD);
    cvt5_kernel<<<(5 * WSZ + 255) / 256, 256>>>(w5, Wq, Wk, Wv, Wb, Wg, WSZ);
    cvtp_kernel<<<(4 * PSZ + 255) / 256, 256>>>(w5 + (size_t)WROWS * DD, Wp1, Wp2, Wp3, PSZ);
    cvt1_kernel<<<(WSZ + 255) / 256, 256>>>(wo, Wo, WSZ);

    // 1) Fused projection: (8192 x 2688) — q,k,v,beta,gamma,p1,p2,p3
    {
        dim3 grid(NPROJ2 / GBN, MM / GBM);
        mma_gemm<<<grid, 256>>>(x, w5, proj, MM, NPROJ2, DD, nullptr);
    }
    // 2) Recurrence (64 threads per (b,h), one barrier per step)
    recur_kernel<<<BB * HH, 64>>>(proj, term, tkp, tvp, sprev, tick, attn);

    // 3) Output projection: out = attn @ Wo^T + bo  (8192 x 512)
    {
        dim3 grid(DD / GBN, MM / GBM);
        mma_gemm<<<grid, 256>>>(attn, wo, (float*)d_out, MM, DD, DD, bo);
    }
}